// round 4
// baseline (speedup 1.0000x reference)
#include <cuda_runtime.h>
#include <math.h>

#define B_ 8
#define N_ 256
#define F_ 59
#define C_ 128
#define G_ 16           // receivers per main block
#define MAXROWS 2048

// ---------------- device scratch ----------------
__device__ float g_v[B_*N_*C_];
__device__ float g_tsrc[B_*N_*C_];
__device__ float g_tdst[B_*N_*C_];
__device__ float g_awfT[C_*C_];   // folded attn_w transposed: [c][d]

// ---------------- packed f32x2 helpers ----------------
__device__ __forceinline__ void fma2(unsigned long long& a,
                                     unsigned long long x, unsigned long long y) {
    asm("fma.rn.f32x2 %0, %1, %2, %0;" : "+l"(a) : "l"(x), "l"(y));
}
__device__ __forceinline__ void unpack2(unsigned long long a, float& lo, float& hi) {
    unsigned int l_, h_;
    asm("mov.b64 {%0, %1}, %2;" : "=r"(l_), "=r"(h_) : "l"(a));
    lo = __uint_as_float(l_); hi = __uint_as_float(h_);
}

// =====================================================================
// Kernel 1: per-node precompute (+ inline BN fold of attn_w, emit awfT)
// grid = 128 (16 nodes each), block = 256 = (c:128) x (g:2)
// =====================================================================
__global__ void __launch_bounds__(256, 1)
precompute_kernel(const float* __restrict__ x,
                  const float* __restrict__ Wl,
                  const float* __restrict__ Ws,
                  const float* __restrict__ Wd,
                  const float* __restrict__ attn_w, const float* __restrict__ attn_b,
                  const float* __restrict__ ag, const float* __restrict__ ab,
                  const float* __restrict__ am, const float* __restrict__ av)
{
    extern __shared__ float sh[];
    float* s_wl = sh;                  // [128][60]
    float* s_ws = s_wl + 128*60;
    float* s_wd = s_ws + 128*60;
    float* s_aw = s_wd + 128*60;       // [128][132] folded
    float* s_x  = s_aw + 128*132;      // [16][64]
    float* s_as = s_x  + 16*64;        // [16][128]
    float* s_ad = s_as + 16*128;       // [16][128]
    float* s_s2 = s_ad + 16*128;       // [128]
    float* s_b2 = s_s2 + 128;          // [128]

    const int t   = threadIdx.x;
    const int blk = blockIdx.x;        // node base = blk*16

    // BN scale/bias for attn
    if (t < 128) {
        float s2 = ag[t] * rsqrtf(av[t] + 1e-5f);
        s_s2[t] = s2;
        s_b2[t] = attn_b[t] * s2 + ab[t] - am[t] * s2;
    }
    __syncthreads();

    // stage projection weights (padded stride 60)
    for (int idx = t; idx < 128*F_; idx += 256) {
        int c = idx / F_, f = idx % F_;
        s_wl[c*60 + f] = Wl[idx];
        s_ws[c*60 + f] = Ws[idx];
        s_wd[c*60 + f] = Wd[idx];
    }
    // fold + stage attn weights (padded stride 132), vectorized
    {
        const float4* aw4 = (const float4*)attn_w;
        for (int i4 = t; i4 < C_*C_/4; i4 += 256) {
            float4 w = aw4[i4];
            int c = i4 >> 5, k = (i4 & 31) * 4;
            float s2 = s_s2[c];
            float* dst = s_aw + c*132 + k;
            dst[0] = w.x*s2; dst[1] = w.y*s2; dst[2] = w.z*s2; dst[3] = w.w*s2;
        }
    }
    // stage x for 16 nodes
    for (int idx = t; idx < 16*F_; idx += 256) {
        int n = idx / F_, f = idx % F_;
        s_x[n*64 + f] = x[blk*16*F_ + idx];
    }
    __syncthreads();

    // export this block's awfT column slice (c = blk)
    if (t < 128) g_awfT[t*C_ + blk] = s_aw[blk*132 + t];

    const int c = t & 127, g = t >> 7;

    // ---- GEMM1: v / a_src / a_dst for 8 nodes ----
    float accv[8], accs[8], accd[8];
#pragma unroll
    for (int n = 0; n < 8; n++) { accv[n] = 0.f; accs[n] = 0.f; accd[n] = 0.f; }

    for (int f4 = 0; f4 < 56; f4 += 4) {
        float4 wl4 = *(const float4*)(s_wl + c*60 + f4);
        float4 ws4 = *(const float4*)(s_ws + c*60 + f4);
        float4 wd4 = *(const float4*)(s_wd + c*60 + f4);
#pragma unroll
        for (int n = 0; n < 8; n++) {
            float4 x4 = *(const float4*)(s_x + (g*8 + n)*64 + f4);
            accv[n] = fmaf(x4.x, wl4.x, fmaf(x4.y, wl4.y, fmaf(x4.z, wl4.z, fmaf(x4.w, wl4.w, accv[n]))));
            accs[n] = fmaf(x4.x, ws4.x, fmaf(x4.y, ws4.y, fmaf(x4.z, ws4.z, fmaf(x4.w, ws4.w, accs[n]))));
            accd[n] = fmaf(x4.x, wd4.x, fmaf(x4.y, wd4.y, fmaf(x4.z, wd4.z, fmaf(x4.w, wd4.w, accd[n]))));
        }
    }
#pragma unroll
    for (int f = 56; f < F_; f++) {
        float wl = s_wl[c*60 + f], ws = s_ws[c*60 + f], wd = s_wd[c*60 + f];
#pragma unroll
        for (int n = 0; n < 8; n++) {
            float xv = s_x[(g*8 + n)*64 + f];
            accv[n] = fmaf(xv, wl, accv[n]);
            accs[n] = fmaf(xv, ws, accs[n]);
            accd[n] = fmaf(xv, wd, accd[n]);
        }
    }
#pragma unroll
    for (int n = 0; n < 8; n++) {
        int node = g*8 + n;
        g_v[(blk*16 + node)*C_ + c] = accv[n];
        s_as[node*128 + c] = accs[n];
        s_ad[node*128 + c] = accd[n];
    }
    __syncthreads();

    // ---- GEMM2: t_src / t_dst ----
    float ts[8], td[8];
#pragma unroll
    for (int n = 0; n < 8; n++) { ts[n] = 0.f; td[n] = 0.f; }

    for (int k4 = 0; k4 < C_; k4 += 4) {
        float4 aw4 = *(const float4*)(s_aw + c*132 + k4);
#pragma unroll
        for (int n = 0; n < 8; n++) {
            float4 a4 = *(const float4*)(s_as + (g*8 + n)*128 + k4);
            float4 d4 = *(const float4*)(s_ad + (g*8 + n)*128 + k4);
            ts[n] = fmaf(a4.x, aw4.x, fmaf(a4.y, aw4.y, fmaf(a4.z, aw4.z, fmaf(a4.w, aw4.w, ts[n]))));
            td[n] = fmaf(d4.x, aw4.x, fmaf(d4.y, aw4.y, fmaf(d4.z, aw4.z, fmaf(d4.w, aw4.w, td[n]))));
        }
    }
    float b2 = s_b2[c];
#pragma unroll
    for (int n = 0; n < 8; n++) {
        int node = g*8 + n;
        g_tsrc[(blk*16 + node)*C_ + c] = ts[n];
        g_tdst[(blk*16 + node)*C_ + c] = td[n] + b2;
    }
}

// =====================================================================
// Kernel 2: fused attention. grid = 128 (16 receivers), block = 512
// =====================================================================
__global__ void __launch_bounds__(512, 1)
main_kernel(const float* __restrict__ pos, const float* __restrict__ nrm,
            const float* __restrict__ rptr,
            const float* __restrict__ pos_w, const float* __restrict__ pos_b,
            const float* __restrict__ pg, const float* __restrict__ pb,
            const float* __restrict__ pm, const float* __restrict__ pv,
            float* __restrict__ out)
{
    extern __shared__ float sh[];
    float* s_awt  = sh;                     // [c][d] 16384 f
    float* s_dt2  = s_awt + C_*C_;          // [c][2*row] dup 8192 f
    float* s_sc   = s_dt2;                  // [row][d] alias (4096 f)
    float* s_val  = s_dt2 + C_*64;          // [row][d] 4096 f
    float* s_relf = s_val + 32*C_;          // [row][9] 288
    float* s_pw   = s_relf + 32*9;          // 768
    float* s_pb   = s_pw + C_*6;            // 128
    float* s_td   = s_pb + C_;              // [ii][d] 2048
    float* s_posn = s_td + G_*C_;           // [j][8] 2048
    int*   s_rows = (int*)(s_posn + 256*8); // MAXROWS
    int*   s_mask = s_rows + MAXROWS;       // [16][16]
    int*   s_woff = s_mask + 256;           // [16][16]
    int*   s_roff = s_woff + 256;           // 17

    const int blk = blockIdx.x;
    const int b  = blk >> 4;
    const int i0 = (blk & 15) * G_;
    const int t  = threadIdx.x;
    const int wd = t >> 5, ln = t & 31;

    // ---- stage constants ----
    {
        const float4* src = (const float4*)g_awfT;
        float4* dst = (float4*)s_awt;
        for (int i4 = t; i4 < C_*C_/4; i4 += 512) dst[i4] = src[i4];
    }
    if (t < C_) {   // fold pos_nn BN inline
        float s1 = pg[t] * rsqrtf(pv[t] + 1e-5f);
        s_pb[t] = pos_b[t] * s1 + pb[t] - pm[t] * s1;
#pragma unroll
        for (int k = 0; k < 6; k++) s_pw[t*6 + k] = pos_w[t*6 + k] * s1;
    }
    for (int idx = t; idx < G_*C_; idx += 512) {
        int ii = idx >> 7, dd = idx & 127;
        s_td[idx] = g_tdst[(b*N_ + i0 + ii)*C_ + dd];
    }
    if (t < 256) {
        const float* pj = pos + (b*N_ + t)*3;
        const float* nj = nrm + (b*N_ + t)*3;
        float* r_ = s_posn + t*8;
        r_[0] = pj[0]; r_[1] = pj[1]; r_[2] = pj[2];
        r_[3] = nj[0]; r_[4] = nj[1]; r_[5] = nj[2];
    }
    __syncthreads();

    float rr;
    { int iv = *(const int*)rptr; rr = (iv > 0 && iv < 1000000) ? (float)iv : *rptr; }
    const float r2 = rr * rr;

    // ---- deterministic sorted compaction ----
    unsigned predbits = 0;
    if (t < 256) {
        float px = s_posn[t*8+0], py = s_posn[t*8+1], pz = s_posn[t*8+2];
#pragma unroll
        for (int ii = 0; ii < G_; ii++) {
            float dx = s_posn[(i0+ii)*8+0] - px;
            float dy = s_posn[(i0+ii)*8+1] - py;
            float dz = s_posn[(i0+ii)*8+2] - pz;
            if (dx*dx + dy*dy + dz*dz <= r2) predbits |= (1u << ii);
        }
    }
#pragma unroll
    for (int ii = 0; ii < G_; ii++) {
        unsigned msk = __ballot_sync(0xFFFFFFFFu, (predbits >> ii) & 1u);
        if (ln == 0) s_mask[ii*16 + wd] = (int)msk;
    }
    __syncthreads();

    if (t < 32) {
        int ii = t;
        int cnt = 0;
        if (ii < 16)
            for (int w = 0; w < 16; w++) cnt += __popc((unsigned)s_mask[ii*16 + w]);
        int incl = cnt;
#pragma unroll
        for (int off = 1; off < 16; off <<= 1) {
            int v = __shfl_up_sync(0xFFFFFFFFu, incl, off);
            if (ln >= off) incl += v;
        }
        if (ii < 16) {
            int excl = incl - cnt;
            s_roff[ii] = excl < MAXROWS ? excl : MAXROWS;
            int run = excl;
            for (int w = 0; w < 16; w++) {
                s_woff[ii*16 + w] = run;
                run += __popc((unsigned)s_mask[ii*16 + w]);
            }
            if (ii == 15) s_roff[16] = run < MAXROWS ? run : MAXROWS;
        }
    }
    __syncthreads();

    if (t < 256) {
#pragma unroll
        for (int ii = 0; ii < G_; ii++) {
            if ((predbits >> ii) & 1u) {
                unsigned msk = (unsigned)s_mask[ii*16 + wd];
                int idx = s_woff[ii*16 + wd] + __popc(msk & ((1u << ln) - 1u));
                if (idx < MAXROWS) s_rows[idx] = t | (ii << 8);
            }
        }
    }
    __syncthreads();
    const int nrows = s_roff[16];
    const int T = (nrows + 31) & ~31;
    if (t < T - nrows) s_rows[nrows + t] = 0;   // benign padding
    __syncthreads();

    // roles
    const int d = t & 127, h = t >> 7;     // epilogue: (d, quarter)
    const int dp = t & 63,  rg = t >> 6;   // matvec: d-pair, row-group(4)

    float pwd[6];
#pragma unroll
    for (int k = 0; k < 6; k++) pwd[k] = s_pw[d*6 + k];
    const float pbd = s_pb[d];
    const float* tsb = g_tsrc + (size_t)(b*N_)*C_;
    const float* vb  = g_v    + (size_t)(b*N_)*C_;

    float l_[4], o_[4];
#pragma unroll
    for (int s = 0; s < 4; s++) { l_[s] = 0.f; o_[s] = 0.f; }

    for (int base = 0; base < T; base += 32) {
        // --- relative geometry (32 rows) ---
        if (t < 32) {
            int tag = s_rows[base + t];
            int j = tag & 255, ii = tag >> 8;
            const float* pj = s_posn + j*8;
            const float* gi = s_posn + (i0 + ii)*8;
            float* rf = s_relf + t*9;
            rf[0] = gi[0] - pj[0];
            rf[1] = gi[1] - pj[1];
            rf[2] = gi[2] - pj[2];
            rf[3] = gi[3] - pj[3];
            rf[4] = gi[4] - pj[4];
            rf[5] = gi[5] - pj[5];
        }
        __syncthreads();

        // --- delta fill, pre-duplicated: s_dt2[c][2*row] = {dv, dv} ---
        {
            int row = t & 31, cg = t >> 5;  // 16 groups x 8 channels
            float rf[6];
#pragma unroll
            for (int k = 0; k < 6; k++) rf[k] = s_relf[row*9 + k];
#pragma unroll
            for (int cc = 0; cc < 8; cc++) {
                int c = cg*8 + cc;
                float dv = s_pb[c];
#pragma unroll
                for (int k = 0; k < 6; k++) dv = fmaf(rf[k], s_pw[c*6 + k], dv);
                dv = fmaxf(dv, 0.f);
                *(float2*)(s_dt2 + c*64 + 2*row) = make_float2(dv, dv);
            }
        }
        __syncthreads();

        // --- matvec: rows rg*4..+3, d-pair dp (7 slots / 8 MAC) ---
        unsigned long long acc0 = 0, acc1 = 0, acc2 = 0, acc3 = 0;
        const float* wbase = s_awt + 2*dp;
        const float* dbase = s_dt2 + 8*rg;
#pragma unroll 4
        for (int c = 0; c < C_; c++) {
            unsigned long long w = *(const unsigned long long*)(wbase + c*C_);
            ulonglong2 d01 = *(const ulonglong2*)(dbase + c*64);
            ulonglong2 d23 = *(const ulonglong2*)(dbase + c*64 + 4);
            fma2(acc0, w, d01.x);
            fma2(acc1, w, d01.y);
            fma2(acc2, w, d23.x);
            fma2(acc3, w, d23.y);
        }
        __syncthreads();   // all s_dt2 reads done before s_sc overwrite (alias)

        {
            float lo, hi;
            unpack2(acc0, lo, hi); *(float2*)(s_sc + (rg*4+0)*C_ + 2*dp) = make_float2(lo, hi);
            unpack2(acc1, lo, hi); *(float2*)(s_sc + (rg*4+1)*C_ + 2*dp) = make_float2(lo, hi);
            unpack2(acc2, lo, hi); *(float2*)(s_sc + (rg*4+2)*C_ + 2*dp) = make_float2(lo, hi);
            unpack2(acc3, lo, hi); *(float2*)(s_sc + (rg*4+3)*C_ + 2*dp) = make_float2(lo, hi);
        }
        __syncthreads();

        // --- E1: batched gather + score/val staging (rows 8h..8h+7) ---
        {
            int tg[8]; float tsv[8], vvv[8];
#pragma unroll
            for (int k = 0; k < 8; k++) {
                int r = h*8 + k;
                int tag = s_rows[base + r];
                tg[k] = tag;
                int j = tag & 255;
                tsv[k] = tsb[j*C_ + d];
                vvv[k] = vb[j*C_ + d];
            }
#pragma unroll
            for (int k = 0; k < 8; k++) {
                int r = h*8 + k;
                int ii = tg[k] >> 8;
                float z = s_sc[r*C_ + d] + s_td[ii*C_ + d] - tsv[k];
                float scv = fmaxf(z, 0.f);
                float dv = pbd;
#pragma unroll
                for (int kk = 0; kk < 6; kk++)
                    dv = fmaf(s_relf[r*9 + kk], pwd[kk], dv);
                dv = fmaxf(dv, 0.f);
                s_sc[r*C_ + d]  = scv;
                s_val[r*C_ + d] = vvv[k] + dv;
            }
        }
        __syncthreads();

        // --- E2: softmax accumulation (scores >= 0, no max shift needed) ---
#pragma unroll
        for (int s = 0; s < 4; s++) {
            int ii = h*4 + s;
            int lo = s_roff[ii]   - base; if (lo < 0)  lo = 0;
            int hi = s_roff[ii+1] - base; if (hi > 32) hi = 32;
            for (int r = lo; r < hi; r++) {
                float e = __expf(s_sc[r*C_ + d]);
                l_[s] += e;
                o_[s] = fmaf(e, s_val[r*C_ + d], o_[s]);
            }
        }
        __syncthreads();
    }

#pragma unroll
    for (int s = 0; s < 4; s++) {
        int ii = h*4 + s;
        out[(b*N_ + i0 + ii)*C_ + d] = o_[s] / l_[s];   // self-loop => l > 0
    }
}

// ---------------- launch ----------------
extern "C" void kernel_launch(void* const* d_in, const int* in_sizes, int n_in,
                              void* d_out, int out_size)
{
    const float* x      = (const float*)d_in[0];
    const float* pos    = (const float*)d_in[1];
    const float* normal = (const float*)d_in[2];
    const float* W_lin  = (const float*)d_in[3];
    const float* W_src  = (const float*)d_in[4];
    const float* W_dst  = (const float*)d_in[5];
    const float* pos_w  = (const float*)d_in[6];
    const float* pos_b  = (const float*)d_in[7];
    const float* pbn_g  = (const float*)d_in[8];
    const float* pbn_b  = (const float*)d_in[9];
    const float* pbn_m  = (const float*)d_in[10];
    const float* pbn_v  = (const float*)d_in[11];
    const float* attn_w = (const float*)d_in[12];
    const float* attn_b = (const float*)d_in[13];
    const float* abn_g  = (const float*)d_in[14];
    const float* abn_b  = (const float*)d_in[15];
    const float* abn_m  = (const float*)d_in[16];
    const float* abn_v  = (const float*)d_in[17];
    const float* rptr   = (const float*)d_in[18];
    float* out = (float*)d_out;

    const size_t smemB = (size_t)(3*128*60 + 128*132 + 16*64 + 2*16*128 + 256) * sizeof(float);
    const size_t smemC = (size_t)(C_*C_ + C_*64 + 32*C_ + 32*9 + C_*6 + C_ + G_*C_ + 256*8) * sizeof(float)
                       + (size_t)(MAXROWS + 256 + 256 + 20) * sizeof(int);

    cudaFuncSetAttribute(precompute_kernel, cudaFuncAttributeMaxDynamicSharedMemorySize, (int)smemB);
    cudaFuncSetAttribute(main_kernel,       cudaFuncAttributeMaxDynamicSharedMemorySize, (int)smemC);
    (void)in_sizes; (void)n_in; (void)out_size;

    precompute_kernel<<<B_*N_/16, 256, smemB>>>(x, W_lin, W_src, W_dst,
                                                attn_w, attn_b, abn_g, abn_b, abn_m, abn_v);
    main_kernel<<<B_*N_/G_, 512, smemC>>>(pos, normal, rptr,
                                          pos_w, pos_b, pbn_g, pbn_b, pbn_m, pbn_v,
                                          out);
}